// round 3
// baseline (speedup 1.0000x reference)
#include <cuda_runtime.h>

// Problem constants (fixed shapes from the reference)
#define T_  1024
#define B_  2
#define N_  10000
#define L_  30
#define S_  61            // 2*L+1

#define NBLK_SQ 1184      // 148 SMs * 8
#define THR_SQ  256

// Scratch (no allocations allowed -> __device__ globals)
__device__ unsigned long long g_sel[B_][T_];
__device__ unsigned long long g_dup[B_][S_];
__device__ int                g_ext[B_][S_];
__device__ float              g_part [NBLK_SQ];
__device__ float              g_part2[B_ * T_];

// ---------------------------------------------------------------------------
// Kernel A: build extended labels, dup masks, and the CTC reachability lattice
// (rf & rb) as per-time uint64 bitmasks. One block.
// ---------------------------------------------------------------------------
__global__ void lattice_kernel(const int* __restrict__ label) {
    __shared__ unsigned long long rf[B_][T_];     // 16 KB
    __shared__ unsigned long long rb[B_][T_];     // 16 KB
    __shared__ int fixf[B_], fixb[B_];
    __shared__ unsigned long long cf[B_], cb[B_];

    const int tid = threadIdx.x;

    // Phase 0: extended (blank-interleaved) labels
    if (tid < B_ * S_) {
        int b = tid / S_, j = tid % S_;
        g_ext[b][j] = (j & 1) ? label[b * L_ + (j >> 1)] : 0;
    }
    __syncthreads();

    // Phase 1: dup[b][j] = bitmask of j' < j with ext[j'] == ext[j]
    if (tid < B_ * S_) {
        int b = tid / S_, j = tid % S_;
        int v = g_ext[b][j];
        unsigned long long d = 0ull;
        for (int j2 = 0; j2 < j; ++j2)
            if (g_ext[b][j2] == v) d |= 1ull << j2;
        g_dup[b][j] = d;
    }
    __syncthreads();

    // Phase 2: serial bitmask scans (one thread per batch), with fixpoint
    const unsigned long long SMASK = (1ull << S_) - 1ull;
    if (tid < B_) {
        const int b = tid;
        unsigned long long allowF = 0ull, allowB = 0ull;
        int e[S_];
        #pragma unroll
        for (int j = 0; j < S_; ++j) e[j] = g_ext[b][j];
        #pragma unroll
        for (int j = 0; j < S_; ++j) {
            if (e[j] != 0 && (j < 2 || e[j] != e[j - 2]))       allowF |= 1ull << j;
            if (e[j] != 0 && (j >= S_ - 2 || e[j] != e[j + 2])) allowB |= 1ull << j;
        }
        // forward reach: start states {0,1}
        unsigned long long c = 3ull;
        rf[b][0] = c;
        int t = 1;
        for (; t < T_; ++t) {
            unsigned long long n = (c | (c << 1) | ((c << 2) & allowF)) & SMASK;
            if (n == c) break;            // saturated
            c = n;
            rf[b][t] = c;
        }
        fixf[b] = t; cf[b] = c;

        // backward reach: start states {S-1, S-2}, stored at times T-1 downward
        c = (1ull << (S_ - 1)) | (1ull << (S_ - 2));
        rb[b][T_ - 1] = c;
        int s = 1;
        for (; s < T_; ++s) {
            unsigned long long n = c | (c >> 1) | ((c >> 2) & allowB);
            if (n == c) break;
            c = n;
            rb[b][T_ - 1 - s] = c;
        }
        fixb[b] = s; cb[b] = c;
    }
    __syncthreads();

    // Phase 3: fill the saturated regions in parallel
    for (int b = 0; b < B_; ++b) {
        for (int t = fixf[b] + tid; t < T_; t += blockDim.x)      rf[b][t] = cf[b];
        for (int t = tid; t < T_ - fixb[b]; t += blockDim.x)      rb[b][t] = cb[b];
    }
    __syncthreads();

    // Phase 4: sel = rf & rb -> global
    for (int i = tid; i < B_ * T_; i += blockDim.x) {
        int b = i >> 10, t = i & (T_ - 1);
        g_sel[b][t] = rf[b][t] & rb[b][t];
    }
}

// ---------------------------------------------------------------------------
// Kernel B: masked sum of squares per (b,t) with dedup over repeated ext values
// ---------------------------------------------------------------------------
__global__ void masked_kernel(const float* __restrict__ logits) {
    const int i = blockIdx.x * blockDim.x + threadIdx.x;
    if (i >= B_ * T_) return;
    const int b = i >> 10, t = i & (T_ - 1);
    const unsigned long long sel = g_sel[b][t];
    const float* __restrict__ row = logits + (size_t)t * (B_ * N_) + (size_t)b * N_;
    float acc = 0.0f;
    unsigned long long m = sel;
    while (m) {
        const int j = __ffsll(m) - 1;
        m &= m - 1;
        // count only the first active state carrying this vocab id
        if ((sel & g_dup[b][j]) == 0ull) {
            const float x = __ldg(row + g_ext[b][j]);
            acc += x * x;
        }
    }
    g_part2[i] = acc;
}

// ---------------------------------------------------------------------------
// Kernel C: full sum of squares (HBM-bound, float4, grid-stride)
// ---------------------------------------------------------------------------
__global__ void __launch_bounds__(THR_SQ) sumsq_kernel(const float4* __restrict__ x) {
    const int total4 = (T_ * B_ * N_) / 4;   // 5,120,000
    float acc = 0.0f;
    for (int i = blockIdx.x * blockDim.x + threadIdx.x; i < total4;
         i += gridDim.x * blockDim.x) {
        const float4 v = x[i];
        acc += v.x * v.x + v.y * v.y + v.z * v.z + v.w * v.w;
    }
    __shared__ float sh[THR_SQ];
    sh[threadIdx.x] = acc;
    __syncthreads();
    #pragma unroll
    for (int s = THR_SQ / 2; s > 0; s >>= 1) {
        if (threadIdx.x < s) sh[threadIdx.x] += sh[threadIdx.x + s];
        __syncthreads();
    }
    if (threadIdx.x == 0) g_part[blockIdx.x] = sh[0];
}

// ---------------------------------------------------------------------------
// Kernel D: deterministic final reduction: out = 0.5 * (sumsq - masked)
// ---------------------------------------------------------------------------
__global__ void finish_kernel(float* __restrict__ out) {
    __shared__ float sh[256];
    float a = 0.0f;
    for (int i = threadIdx.x; i < NBLK_SQ;  i += 256) a += g_part[i];
    for (int i = threadIdx.x; i < B_ * T_;  i += 256) a -= g_part2[i];
    sh[threadIdx.x] = a;
    __syncthreads();
    #pragma unroll
    for (int s = 128; s > 0; s >>= 1) {
        if (threadIdx.x < s) sh[threadIdx.x] += sh[threadIdx.x + s];
        __syncthreads();
    }
    if (threadIdx.x == 0) out[0] = 0.5f * sh[0];
}

// ---------------------------------------------------------------------------
extern "C" void kernel_launch(void* const* d_in, const int* in_sizes, int n_in,
                              void* d_out, int out_size) {
    // Identify inputs by size (robust to metadata ordering):
    // logits: T*B*N floats; label: B*L ints
    const float* logits = nullptr;
    const int*   label  = nullptr;
    for (int i = 0; i < n_in; ++i) {
        if (in_sizes[i] == T_ * B_ * N_) logits = (const float*)d_in[i];
        else if (in_sizes[i] == B_ * L_) label  = (const int*)d_in[i];
    }
    if (!logits) logits = (const float*)d_in[0];
    if (!label)  label  = (const int*)d_in[2];

    float* out = (float*)d_out;

    lattice_kernel<<<1, 128>>>(label);
    masked_kernel<<<(B_ * T_ + 255) / 256, 256>>>(logits);
    sumsq_kernel<<<NBLK_SQ, THR_SQ>>>((const float4*)logits);
    finish_kernel<<<1, 256>>>(out);
}

// round 5
// speedup vs baseline: 1.0658x; 1.0658x over previous
#include <cuda_runtime.h>

// Problem constants (fixed shapes from the reference)
#define T_  1024
#define B_  2
#define N_  10000
#define L_  30
#define S_  61            // 2*L+1

#define NBLK 1184         // 148 SMs * 8
#define THR  256
#define MASK_BLOCKS 8     // MASK_BLOCKS*THR == B_*T_ == 2048 masked rows

// Scratch (no allocations allowed -> __device__ globals)
__device__ unsigned long long g_sel[B_][T_];
__device__ unsigned long long g_dup[B_][S_];
__device__ int                g_ext[B_][S_];
__device__ float              g_part [NBLK];
__device__ float              g_part2[B_ * T_];
__device__ unsigned int       g_count;

// ---------------------------------------------------------------------------
// Kernel A: build extended labels, dup masks, and the CTC reachability lattice
// (rf & rb) as per-time uint64 bitmasks. One block. Also resets the ticket.
// ---------------------------------------------------------------------------
__global__ void lattice_kernel(const int* __restrict__ label) {
    __shared__ unsigned long long rf[B_][T_];     // 16 KB
    __shared__ unsigned long long rb[B_][T_];     // 16 KB
    __shared__ int fixf[B_], fixb[B_];
    __shared__ unsigned long long cf[B_], cb[B_];

    const int tid = threadIdx.x;
    if (tid == 0) g_count = 0u;   // reset ticket for the fused kernel

    // Phase 0: extended (blank-interleaved) labels
    if (tid < B_ * S_) {
        int b = tid / S_, j = tid % S_;
        g_ext[b][j] = (j & 1) ? label[b * L_ + (j >> 1)] : 0;
    }
    __syncthreads();

    // Phase 1: dup[b][j] = bitmask of j' < j with ext[j'] == ext[j]
    if (tid < B_ * S_) {
        int b = tid / S_, j = tid % S_;
        int v = g_ext[b][j];
        unsigned long long d = 0ull;
        for (int j2 = 0; j2 < j; ++j2)
            if (g_ext[b][j2] == v) d |= 1ull << j2;
        g_dup[b][j] = d;
    }
    __syncthreads();

    // Phase 2: serial bitmask scans (one thread per batch), with fixpoint
    const unsigned long long SMASK = (1ull << S_) - 1ull;
    if (tid < B_) {
        const int b = tid;
        unsigned long long allowF = 0ull, allowB = 0ull;
        int e[S_];
        #pragma unroll
        for (int j = 0; j < S_; ++j) e[j] = g_ext[b][j];
        #pragma unroll
        for (int j = 0; j < S_; ++j) {
            if (e[j] != 0 && (j < 2 || e[j] != e[j - 2]))       allowF |= 1ull << j;
            if (e[j] != 0 && (j >= S_ - 2 || e[j] != e[j + 2])) allowB |= 1ull << j;
        }
        // forward reach: start states {0,1}
        unsigned long long c = 3ull;
        rf[b][0] = c;
        int t = 1;
        for (; t < T_; ++t) {
            unsigned long long n = (c | (c << 1) | ((c << 2) & allowF)) & SMASK;
            if (n == c) break;            // saturated
            c = n;
            rf[b][t] = c;
        }
        fixf[b] = t; cf[b] = c;

        // backward reach: start states {S-1, S-2}, stored at times T-1 downward
        c = (1ull << (S_ - 1)) | (1ull << (S_ - 2));
        rb[b][T_ - 1] = c;
        int s = 1;
        for (; s < T_; ++s) {
            unsigned long long n = c | (c >> 1) | ((c >> 2) & allowB);
            if (n == c) break;
            c = n;
            rb[b][T_ - 1 - s] = c;
        }
        fixb[b] = s; cb[b] = c;
    }
    __syncthreads();

    // Phase 3: fill the saturated regions in parallel
    for (int b = 0; b < B_; ++b) {
        for (int t = fixf[b] + tid; t < T_; t += blockDim.x)      rf[b][t] = cf[b];
        for (int t = tid; t < T_ - fixb[b]; t += blockDim.x)      rb[b][t] = cb[b];
    }
    __syncthreads();

    // Phase 4: sel = rf & rb -> global
    for (int i = tid; i < B_ * T_; i += blockDim.x) {
        int b = i >> 10, t = i & (T_ - 1);
        g_sel[b][t] = rf[b][t] & rb[b][t];
    }
}

// ---------------------------------------------------------------------------
// Kernel B (fused): full sum of squares + masked rows + last-block finish.
// Deterministic: final sum is accumulated in fixed index order by whichever
// block takes the last ticket.
// ---------------------------------------------------------------------------
__global__ void __launch_bounds__(THR) fused_kernel(const float4* __restrict__ x4,
                                                    const float*  __restrict__ logits,
                                                    float* __restrict__ out) {
    // --- masked rows: blocks 0..MASK_BLOCKS-1, one (b,t) row per thread ---
    if (blockIdx.x < MASK_BLOCKS) {
        const int i = blockIdx.x * THR + threadIdx.x;      // 0..2047
        const int b = i >> 10, t = i & (T_ - 1);
        const unsigned long long sel = g_sel[b][t];
        const float* __restrict__ row = logits + (size_t)t * (B_ * N_) + (size_t)b * N_;
        float acc2 = 0.0f;
        unsigned long long m = sel;
        while (m) {
            const int j = __ffsll(m) - 1;
            m &= m - 1;
            if ((sel & g_dup[b][j]) == 0ull) {             // dedup repeated vocab ids
                const float v = __ldg(row + g_ext[b][j]);
                acc2 += v * v;
            }
        }
        g_part2[i] = acc2;
    }

    // --- grid-stride full sum of squares (HBM-bound) ---
    const int total4 = (T_ * B_ * N_) / 4;                 // 5,120,000
    float acc = 0.0f;
    for (int i = blockIdx.x * THR + threadIdx.x; i < total4; i += gridDim.x * THR) {
        const float4 v = x4[i];
        acc += v.x * v.x + v.y * v.y + v.z * v.z + v.w * v.w;
    }

    __shared__ float sh[THR];
    sh[threadIdx.x] = acc;
    __syncthreads();
    #pragma unroll
    for (int s = THR / 2; s > 0; s >>= 1) {
        if (threadIdx.x < s) sh[threadIdx.x] += sh[threadIdx.x + s];
        __syncthreads();
    }
    if (threadIdx.x == 0) g_part[blockIdx.x] = sh[0];

    // --- last-block finish (threadFenceReduction pattern) ---
    __shared__ bool is_last;
    __threadfence();
    __syncthreads();
    if (threadIdx.x == 0) {
        const unsigned int ticket = atomicAdd(&g_count, 1u);
        is_last = (ticket == gridDim.x - 1);
    }
    __syncthreads();

    if (is_last) {
        float a = 0.0f;
        for (int i = threadIdx.x; i < NBLK;    i += THR) a += g_part[i];
        for (int i = threadIdx.x; i < B_ * T_; i += THR) a -= g_part2[i];
        __syncthreads();                // sh reuse barrier
        sh[threadIdx.x] = a;
        __syncthreads();
        #pragma unroll
        for (int s = THR / 2; s > 0; s >>= 1) {
            if (threadIdx.x < s) sh[threadIdx.x] += sh[threadIdx.x + s];
            __syncthreads();
        }
        if (threadIdx.x == 0) out[0] = 0.5f * sh[0];
    }
}

// ---------------------------------------------------------------------------
extern "C" void kernel_launch(void* const* d_in, const int* in_sizes, int n_in,
                              void* d_out, int out_size) {
    // Identify inputs by size (robust to metadata ordering):
    const float* logits = nullptr;
    const int*   label  = nullptr;
    for (int i = 0; i < n_in; ++i) {
        if (in_sizes[i] == T_ * B_ * N_) logits = (const float*)d_in[i];
        else if (in_sizes[i] == B_ * L_) label  = (const int*)d_in[i];
    }
    if (!logits) logits = (const float*)d_in[0];
    if (!label)  label  = (const int*)d_in[2];

    float* out = (float*)d_out;

    lattice_kernel<<<1, 128>>>(label);
    fused_kernel<<<NBLK, THR>>>((const float4*)logits, logits, out);
}